// round 8
// baseline (speedup 1.0000x reference)
#include <cuda_runtime.h>
#include <cuda_fp16.h>
#include <cstdint>

// ---------------- problem constants ----------------
#define INDIM 4096
#define NGRP  16
#define NOUT  256

// ---------------- device scratch ----------------
__device__ float  g_cmid[NGRP][128];        // folded constants
__device__ uint2  g_WmF[NGRP][16][16][32];  // mid B frags: [g][n8][k16][lane] -> (b0,b1)
__device__ uint2  g_WrF[32][128][32];       // root B frags: [n8][k16][lane] -> (b0,b1)
__device__ uint4  g_midP[1024][128][32];    // root A frags: [b16][k16][lane] -> (a0..a3)

// ---------------- helpers ----------------
__device__ __forceinline__ void mma16816(float* c, const unsigned* a, unsigned b0, unsigned b1) {
    asm volatile(
        "mma.sync.aligned.m16n8k16.row.col.f32.f16.f16.f32 "
        "{%0,%1,%2,%3},{%4,%5,%6,%7},{%8,%9},{%0,%1,%2,%3};"
        : "+f"(c[0]), "+f"(c[1]), "+f"(c[2]), "+f"(c[3])
        : "r"(a[0]), "r"(a[1]), "r"(a[2]), "r"(a[3]), "r"(b0), "r"(b1));
}
__device__ __forceinline__ float fast_tanh(float v) {
    v = fminf(fmaxf(v, -15.f), 15.f);
    float e = __expf(2.f * v);
    return __fdividef(e - 1.f, e + 1.f);
}
__device__ __forceinline__ unsigned packf2(float lo, float hi) {
    __half2 h = __floats2half2_rn(lo, hi);
    return *(unsigned*)&h;
}

// ---------------- prep ----------------
// blocks [0,256):   cmid constants (warp per (g,n))
// blocks [256,272): g_WmF frag layout (one block per group, smem-transposed)
// blocks [272,304): g_WrF frag layout (64-k slab per block)
__global__ void k_prep(const float* __restrict__ w_inp, const float* __restrict__ pbias,
                       const float* __restrict__ W_mid, const float* __restrict__ b_mid,
                       const float* __restrict__ W_root) {
    extern __shared__ float sm[];
    int tid = threadIdx.x;
    if (blockIdx.x < 256) {
        int w = (blockIdx.x * 256 + tid) >> 5;
        int lane = tid & 31;
        int g = w >> 7, n = w & 127;
        float sum = 0.f;
#pragma unroll
        for (int l = 0; l < 8; l++) {
            int j = l * 32 + lane;
            sum += pbias[(g * 256 + j) >> 6] * W_mid[(g * 256 + j) * 128 + n];
        }
#pragma unroll
        for (int o = 16; o > 0; o >>= 1) sum += __shfl_xor_sync(0xffffffffu, sum, o);
        if (lane == 0) g_cmid[g][n] = sum + b_mid[g * 128 + n];
    } else if (blockIdx.x < 272) {
        int g = blockIdx.x - 256;
        __half* smh = (__half*)sm;               // [256][132] halves = 67584 B
#pragma unroll
        for (int i = 0; i < 128; i++) {
            int flat = i * 256 + tid;
            int k = flat >> 7, n = flat & 127;
            smh[k * 132 + n] = __float2half_rn(w_inp[g * 256 + k] *
                                               W_mid[(g * 256 + k) * 128 + n]);
        }
        __syncthreads();
        int lane = tid & 31, w = tid >> 5;       // 8 warps x 32 tiles = 256 (n8,k16)
#pragma unroll
        for (int i = 0; i < 32; i++) {
            int t = w * 32 + i;
            int n8 = t & 15, k16 = t >> 4;
            int n = n8 * 8 + (lane >> 2);
            int k = k16 * 16 + ((lane & 3) << 1);
            unsigned w0 = packf2(__half2float(smh[k * 132 + n]),
                                 __half2float(smh[(k + 1) * 132 + n]));
            unsigned w1 = packf2(__half2float(smh[(k + 8) * 132 + n]),
                                 __half2float(smh[(k + 9) * 132 + n]));
            g_WmF[g][n8][k16][lane] = make_uint2(w0, w1);
        }
    } else {
        int kb = blockIdx.x - 272;               // 0..31, k slab
#pragma unroll
        for (int j = 0; j < 64; j++) {
            int flat = j * 256 + tid;
            int kl = flat >> 8, n = flat & 255;
            sm[kl * 257 + n] = W_root[(kb * 64 + kl) * 256 + n];
        }
        __syncthreads();
        int lane = tid & 31, w = tid >> 5;
#pragma unroll
        for (int i = 0; i < 16; i++) {
            int t = w * 16 + i;
            int n8 = t & 31, k16l = t >> 5;
            unsigned wd[2];
#pragma unroll
            for (int j = 0; j < 2; j++) {
                int kl = k16l * 16 + j * 8 + ((lane & 3) << 1);
                int n = n8 * 8 + (lane >> 2);
                wd[j] = packf2(sm[kl * 257 + n], sm[(kl + 1) * 257 + n]);
            }
            g_WrF[n8][kb * 4 + k16l][lane] = make_uint2(wd[0], wd[1]);
        }
    }
}

// ================= MID GEMM: 64 rows x 128 n x K=256, smem-free frag-direct ============
// 256 threads, 8 warps: Mw=2 x Nw=4, warp tile 32x32. No smem, no barriers.
__global__ void __launch_bounds__(256) k_mid(const float* __restrict__ x) {
    const int tid = threadIdx.x, lane = tid & 31, wid = tid >> 5;
    const int wmi = wid & 1, wni = wid >> 1;      // 2 M-warps x 4 N-warps
    const long long b0 = (long long)blockIdx.x * 64;
    const int g = blockIdx.y;

    // A: x row base (this lane), col base (this lane); frag words via fixed offsets
    const float* xp = x + (b0 + wmi * 32 + (lane >> 2)) * INDIM + g * 256 + ((lane & 3) << 1);
    // B: frag pointer
    const uint2* bp = &g_WmF[g][wni * 4][0][lane];   // + nt*512 + k16*32 (uint2 units)

    float macc[2][4][4];
#pragma unroll
    for (int i = 0; i < 2; i++)
#pragma unroll
        for (int j = 0; j < 4; j++)
#pragma unroll
            for (int q = 0; q < 4; q++) macc[i][j][q] = 0.f;

    float2 xa[2][2][4];     // [buf][mt][word]  a0,a1,a2,a3 raw f32 pairs
    uint2 bf[2][4];         // [buf][nt]

#define LDX(BUF, K)                                                                   \
    { _Pragma("unroll") for (int mt = 0; mt < 2; mt++) {                              \
          const float* p = xp + mt * 16 * INDIM + (K) * 16;                           \
          xa[BUF][mt][0] = *(const float2*)(p);                                       \
          xa[BUF][mt][1] = *(const float2*)(p + 8 * INDIM);                           \
          xa[BUF][mt][2] = *(const float2*)(p + 8);                                   \
          xa[BUF][mt][3] = *(const float2*)(p + 8 * INDIM + 8);                       \
      } }
#define LDB(BUF, K)                                                                   \
    { _Pragma("unroll") for (int nt = 0; nt < 4; nt++)                                \
          bf[BUF][nt] = bp[nt * 512 + (K) * 32]; }
#define MM(BUF)                                                                       \
    { _Pragma("unroll") for (int mt = 0; mt < 2; mt++) {                              \
          unsigned aw[4];                                                             \
          _Pragma("unroll") for (int j = 0; j < 4; j++)                               \
              aw[j] = packf2(xa[BUF][mt][j].x, xa[BUF][mt][j].y);                     \
          _Pragma("unroll") for (int nt = 0; nt < 4; nt++)                            \
              mma16816(macc[mt][nt], aw, bf[BUF][nt].x, bf[BUF][nt].y);               \
      } }

    LDX(0, 0); LDB(0, 0);
#pragma unroll 1
    for (int ks = 0; ks < 16; ks += 2) {
        LDX(1, ks + 1); LDB(1, ks + 1);
        MM(0);
        if (ks + 2 < 16) { LDX(0, ks + 2); LDB(0, ks + 2); }
        MM(1);
    }

    // epilogue: tanh + pack macc directly into A-frag tiles (no smem)
    const int nbase = wni * 32 + ((lane & 3) << 1);
#pragma unroll
    for (int mt = 0; mt < 2; mt++) {
        int b16 = (int)(b0 >> 4) + wmi * 2 + mt;
#pragma unroll
        for (int ntp = 0; ntp < 2; ntp++) {
            unsigned wd[4];
#pragma unroll
            for (int h = 0; h < 2; h++) {
                int nt = ntp * 2 + h;
                float2 gc = *(const float2*)&g_cmid[g][nbase + nt * 8];
                float* cc = macc[mt][nt];
                wd[2 * h]     = packf2(fast_tanh(cc[0] + gc.x), fast_tanh(cc[1] + gc.y));
                wd[2 * h + 1] = packf2(fast_tanh(cc[2] + gc.x), fast_tanh(cc[3] + gc.y));
            }
            g_midP[b16][g * 8 + wni * 2 + ntp][lane] = make_uint4(wd[0], wd[1], wd[2], wd[3]);
        }
    }
}

// ================= ROOT GEMM: 128 rows x 256 n x K=2048, smem-free frag-direct ==========
__global__ void __launch_bounds__(512) k_root(float* __restrict__ out,
                                              const float* __restrict__ b_root) {
    const int tid = threadIdx.x, lane = tid & 31, wid = tid >> 5;
    const int wmi = wid & 1, wni = wid >> 1;      // 2 M-warps x 8 N-warps
    const long long b0 = (long long)blockIdx.x * 128;
    const int bt = blockIdx.x * 8;

    float racc[4][4][4];
#pragma unroll
    for (int i = 0; i < 4; i++)
#pragma unroll
        for (int j = 0; j < 4; j++)
#pragma unroll
            for (int q = 0; q < 4; q++) racc[i][j][q] = 0.f;

    const char* Ap = (const char*)&g_midP[bt + wmi * 4][0][lane];   // + mt*65536 + ks*512
    const char* Bp = (const char*)&g_WrF[wni * 4][0][lane];         // + nt*32768 + ks*256

    uint4 Af[2][4];
    uint2 Bf[2][4];
#define RLDA(BUF, KS)                                                                \
    { _Pragma("unroll") for (int mt = 0; mt < 4; mt++)                               \
          Af[BUF][mt] = *(const uint4*)(Ap + mt * 65536 + (KS) * 512); }
#define RLDB(BUF, KS)                                                                \
    { _Pragma("unroll") for (int nt = 0; nt < 4; nt++)                               \
          Bf[BUF][nt] = *(const uint2*)(Bp + nt * 32768 + (KS) * 256); }
#define RMMAS(BUF)                                                                   \
    { _Pragma("unroll") for (int mt = 0; mt < 4; mt++)                               \
          _Pragma("unroll") for (int nt = 0; nt < 4; nt++)                           \
              mma16816(racc[mt][nt], (const unsigned*)&Af[BUF][mt],                  \
                       Bf[BUF][nt].x, Bf[BUF][nt].y); }

    RLDA(0, 0); RLDB(0, 0);
#pragma unroll 1
    for (int ks = 0; ks < 128; ks += 2) {
        RLDA(1, ks + 1); RLDB(1, ks + 1);
        RMMAS(0);
        if (ks + 2 < 128) { RLDA(0, ks + 2); RLDB(0, ks + 2); }
        RMMAS(1);
    }

#pragma unroll
    for (int mt = 0; mt < 4; mt++)
#pragma unroll
        for (int nt = 0; nt < 4; nt++) {
            int row = wmi * 64 + mt * 16 + (lane >> 2);
            int n = wni * 32 + nt * 8 + ((lane & 3) << 1);
            float2 br = *(const float2*)&b_root[n];
            *(float2*)&out[(b0 + row) * NOUT + n] =
                make_float2(racc[mt][nt][0] + br.x, racc[mt][nt][1] + br.y);
            *(float2*)&out[(b0 + row + 8) * NOUT + n] =
                make_float2(racc[mt][nt][2] + br.x, racc[mt][nt][3] + br.y);
        }
}

// ---------------- launch ----------------
extern "C" void kernel_launch(void* const* d_in, const int* in_sizes, int n_in,
                              void* d_out, int out_size) {
    const float* x      = (const float*)d_in[0];
    const float* w_inp  = (const float*)d_in[1];
    const float* pbias  = (const float*)d_in[2];
    const float* W_mid  = (const float*)d_in[3];
    const float* b_mid  = (const float*)d_in[4];
    const float* W_root = (const float*)d_in[5];
    const float* b_root = (const float*)d_in[6];
    float* out = (float*)d_out;

    int batch = in_sizes[0] / INDIM;   // 16384

    const int PREP_SMEM = 256 * 132 * 2;   // 67584 (covers both transpose stages)
    cudaFuncSetAttribute(k_prep, cudaFuncAttributeMaxDynamicSharedMemorySize, PREP_SMEM);

    k_prep<<<304, 256, PREP_SMEM>>>(w_inp, pbias, W_mid, b_mid, W_root);
    k_mid<<<dim3(batch / 64, NGRP), 256>>>(x);
    k_root<<<batch / 128, 512>>>(out, b_root);
}

// round 9
// speedup vs baseline: 1.0845x; 1.0845x over previous
#include <cuda_runtime.h>
#include <cuda_fp16.h>
#include <cstdint>

// ---------------- problem constants ----------------
#define INDIM 4096
#define NGRP  16
#define NOUT  256

// ---------------- device scratch ----------------
__device__ float  g_cmid[NGRP][128];        // folded constants
__device__ uint2  g_WmF[NGRP][16][16][32];  // mid B frags: [g][n8][k16][lane] -> (b0,b1)
__device__ uint2  g_WrF[32][128][32];       // root B frags: [n8][k16][lane] -> (b0,b1)
__device__ uint4  g_midP[1024][128][32];    // root A frags: [b16][k16][lane] -> (a0..a3)

// ---------------- helpers ----------------
__device__ __forceinline__ unsigned smem_u32(const void* p) {
    unsigned a;
    asm("{ .reg .u64 t; cvta.to.shared.u64 t, %1; cvt.u32.u64 %0, t; }" : "=r"(a) : "l"(p));
    return a;
}
__device__ __forceinline__ void ldsm4(unsigned& r0, unsigned& r1, unsigned& r2, unsigned& r3,
                                      unsigned addr) {
    asm volatile("ldmatrix.sync.aligned.m8n8.x4.shared.b16 {%0,%1,%2,%3}, [%4];"
                 : "=r"(r0), "=r"(r1), "=r"(r2), "=r"(r3) : "r"(addr));
}
__device__ __forceinline__ void mma16816(float* c, const unsigned* a, unsigned b0, unsigned b1) {
    asm volatile(
        "mma.sync.aligned.m16n8k16.row.col.f32.f16.f16.f32 "
        "{%0,%1,%2,%3},{%4,%5,%6,%7},{%8,%9},{%0,%1,%2,%3};"
        : "+f"(c[0]), "+f"(c[1]), "+f"(c[2]), "+f"(c[3])
        : "r"(a[0]), "r"(a[1]), "r"(a[2]), "r"(a[3]), "r"(b0), "r"(b1));
}
__device__ __forceinline__ float fast_tanh(float v) {
    v = fminf(fmaxf(v, -15.f), 15.f);
    float e = __expf(2.f * v);
    return __fdividef(e - 1.f, e + 1.f);
}
__device__ __forceinline__ unsigned packf2(float lo, float hi) {
    __half2 h = __floats2half2_rn(lo, hi);
    return *(unsigned*)&h;
}

// ---------------- prep ----------------
// blocks [0,16):  g_WmF frag layout + g_cmid (one block per group)
// blocks [16,48): g_WrF frag layout (64-k slab per block)
__global__ void k_prep(const float* __restrict__ w_inp, const float* __restrict__ pbias,
                       const float* __restrict__ W_mid, const float* __restrict__ b_mid,
                       const float* __restrict__ W_root) {
    extern __shared__ float sm[];
    int tid = threadIdx.x;
    if (blockIdx.x < 16) {
        int g = blockIdx.x;
        __half* smh = (__half*)sm;               // [256 k][132 n] halves = 67584 B
        float part = 0.f;
#pragma unroll
        for (int i = 0; i < 128; i++) {
            int flat = i * 256 + tid;
            int k = flat >> 7, n = flat & 127;
            float wmv = W_mid[(g * 256 + k) * 128 + n];
            smh[k * 132 + n] = __float2half_rn(w_inp[g * 256 + k] * wmv);
            part += pbias[(g * 256 + k) >> 6] * wmv;
        }
        float* pb = (float*)(sm + 16896);        // after 67584 B of halves
        pb[tid] = part;
        __syncthreads();
        if (tid < 128) g_cmid[g][tid] = pb[tid] + pb[tid + 128] + b_mid[g * 128 + tid];
        int lane = tid & 31, w = tid >> 5;       // 8 warps x 32 tiles = 256 (n8,k16)
#pragma unroll
        for (int i = 0; i < 32; i++) {
            int t = w * 32 + i;
            int n8 = t & 15, k16 = t >> 4;
            int n = n8 * 8 + (lane >> 2);
            int k = k16 * 16 + ((lane & 3) << 1);
            unsigned w0 = packf2(__half2float(smh[k * 132 + n]),
                                 __half2float(smh[(k + 1) * 132 + n]));
            unsigned w1 = packf2(__half2float(smh[(k + 8) * 132 + n]),
                                 __half2float(smh[(k + 9) * 132 + n]));
            g_WmF[g][n8][k16][lane] = make_uint2(w0, w1);
        }
    } else {
        int kb = blockIdx.x - 16;                // 0..31, k slab
#pragma unroll
        for (int j = 0; j < 64; j++) {
            int flat = j * 256 + tid;
            int kl = flat >> 8, n = flat & 255;
            sm[kl * 257 + n] = W_root[(kb * 64 + kl) * 256 + n];
        }
        __syncthreads();
        int lane = tid & 31, w = tid >> 5;
#pragma unroll
        for (int i = 0; i < 16; i++) {
            int t = w * 16 + i;
            int n8 = t & 31, k16l = t >> 5;
            unsigned wd[2];
#pragma unroll
            for (int j = 0; j < 2; j++) {
                int kl = k16l * 16 + j * 8 + ((lane & 3) << 1);
                int n = n8 * 8 + (lane >> 2);
                wd[j] = packf2(sm[kl * 257 + n], sm[(kl + 1) * 257 + n]);
            }
            g_WrF[n8][kb * 4 + k16l][lane] = make_uint2(wd[0], wd[1]);
        }
    }
}

// ================= MID GEMM: 128 rows/CTA, all 16 groups in-CTA, one wave ============
// 512 threads, 16 warps: Mw=2 (64 rows) x Nw=8 (16 n). A via smem+ldsm, B frag-direct.
// smem: 2 x [128][72] f16 = 36864 B (x staging double buffer)
#define MXSTR 72
#define MXBUF 18432u
#define MID_SMEM 36864

__global__ void __launch_bounds__(512) k_mid(const float* __restrict__ x) {
    extern __shared__ char smem[];
    unsigned sb = smem_u32(smem);
    const int tid = threadIdx.x, lane = tid & 31, wid = tid >> 5;
    const int wmi = wid & 1, wni = wid >> 1;      // 2 M-warps x 8 N-warps
    const long long b0 = (long long)blockIdx.x * 128;
    const int b16b = blockIdx.x * 8;

    // x LDG mapping: idx = tid + j*512 over 2048 float4 of a [128][64] f32 chunk
    // row = idx>>4, f4 = idx&15 (coalesced 256B per 16 threads)
    float4 xv[4];
#define LDXCHUNK(CC)                                                                  \
    { int kg = (CC) * 64;                                                             \
      _Pragma("unroll") for (int j = 0; j < 4; j++) {                                 \
          int idx = tid + j * 512;                                                    \
          int r = idx >> 4, f4 = idx & 15;                                            \
          xv[j] = *(const float4*)(x + (b0 + r) * INDIM + kg + f4 * 4);               \
      } }
#define STSCHUNK(BUF)                                                                 \
    { unsigned xbuf = sb + (BUF) * MXBUF;                                             \
      _Pragma("unroll") for (int j = 0; j < 4; j++) {                                 \
          int idx = tid + j * 512;                                                    \
          int r = idx >> 4, f4 = idx & 15;                                            \
          unsigned h0 = packf2(xv[j].x, xv[j].y), h1 = packf2(xv[j].z, xv[j].w);      \
          asm volatile("st.shared.v2.b32 [%0], {%1,%2};"                              \
                       :: "r"(xbuf + (unsigned)(r * MXSTR + f4 * 4) * 2u),            \
                          "r"(h0), "r"(h1));                                          \
      } }

    LDXCHUNK(0);

    for (int g = 0; g < NGRP; g++) {
        const uint2* bp = &g_WmF[g][wni * 2][0][lane];   // + nt*512 + k16*32 (uint2)

        float macc[4][2][4];
#pragma unroll
        for (int i = 0; i < 4; i++)
#pragma unroll
            for (int j = 0; j < 2; j++)
#pragma unroll
                for (int q = 0; q < 4; q++) macc[i][j][q] = 0.f;

#pragma unroll
        for (int c = 0; c < 4; c++) {
            const int buf = c & 1;
            STSCHUNK(buf);
            int cc_next = g * 4 + c + 1;
            if (cc_next < NGRP * 4) LDXCHUNK(cc_next);
            __syncthreads();

            // B frags for the whole chunk (8 coalesced LDG.64, latency hidden by MLP)
            uint2 bf[4][2];
#pragma unroll
            for (int ks = 0; ks < 4; ks++)
#pragma unroll
                for (int nt = 0; nt < 2; nt++)
                    bf[ks][nt] = bp[nt * 512 + (c * 4 + ks) * 32];

            unsigned xbuf = sb + buf * MXBUF;
            int arow = wmi * 64 + (lane & 15);
            int acol = ((lane >> 4) << 3);
#pragma unroll
            for (int ks = 0; ks < 4; ks++) {
                unsigned afr[4][4];
#pragma unroll
                for (int mt = 0; mt < 4; mt++)
                    ldsm4(afr[mt][0], afr[mt][1], afr[mt][2], afr[mt][3],
                          xbuf + (unsigned)((arow + mt * 16) * MXSTR + ks * 16 + acol) * 2u);
#pragma unroll
                for (int mt = 0; mt < 4; mt++)
#pragma unroll
                    for (int nt = 0; nt < 2; nt++)
                        mma16816(macc[mt][nt], afr[mt], bf[ks][nt].x, bf[ks][nt].y);
            }
        }

        // epilogue: tanh + pack directly into root A-frag tiles (no smem, no sync)
        const int nb = wni * 16 + ((lane & 3) << 1);
#pragma unroll
        for (int mt = 0; mt < 4; mt++) {
            unsigned wd[4];
#pragma unroll
            for (int nt = 0; nt < 2; nt++) {
                float2 gc = *(const float2*)&g_cmid[g][nb + nt * 8];
                float* cc = macc[mt][nt];
                wd[2 * nt]     = packf2(fast_tanh(cc[0] + gc.x), fast_tanh(cc[1] + gc.y));
                wd[2 * nt + 1] = packf2(fast_tanh(cc[2] + gc.x), fast_tanh(cc[3] + gc.y));
            }
            g_midP[b16b + wmi * 4 + mt][g * 8 + wni][lane] =
                make_uint4(wd[0], wd[1], wd[2], wd[3]);
        }
    }
}

// ================= ROOT GEMM: 128 rows x 256 n x K=2048, smem-free frag-direct ==========
__global__ void __launch_bounds__(512) k_root(float* __restrict__ out,
                                              const float* __restrict__ b_root) {
    const int tid = threadIdx.x, lane = tid & 31, wid = tid >> 5;
    const int wmi = wid & 1, wni = wid >> 1;      // 2 M-warps x 8 N-warps
    const long long b0 = (long long)blockIdx.x * 128;
    const int bt = blockIdx.x * 8;

    float racc[4][4][4];
#pragma unroll
    for (int i = 0; i < 4; i++)
#pragma unroll
        for (int j = 0; j < 4; j++)
#pragma unroll
            for (int q = 0; q < 4; q++) racc[i][j][q] = 0.f;

    const char* Ap = (const char*)&g_midP[bt + wmi * 4][0][lane];   // + mt*65536 + ks*512
    const char* Bp = (const char*)&g_WrF[wni * 4][0][lane];         // + nt*32768 + ks*256

    uint4 Af[2][4];
    uint2 Bf[2][4];
#define RLDA(BUF, KS)                                                                \
    { _Pragma("unroll") for (int mt = 0; mt < 4; mt++)                               \
          Af[BUF][mt] = *(const uint4*)(Ap + mt * 65536 + (KS) * 512); }
#define RLDB(BUF, KS)                                                                \
    { _Pragma("unroll") for (int nt = 0; nt < 4; nt++)                               \
          Bf[BUF][nt] = *(const uint2*)(Bp + nt * 32768 + (KS) * 256); }
#define RMMAS(BUF)                                                                   \
    { _Pragma("unroll") for (int mt = 0; mt < 4; mt++)                               \
          _Pragma("unroll") for (int nt = 0; nt < 4; nt++)                           \
              mma16816(racc[mt][nt], (const unsigned*)&Af[BUF][mt],                  \
                       Bf[BUF][nt].x, Bf[BUF][nt].y); }

    RLDA(0, 0); RLDB(0, 0);
#pragma unroll 1
    for (int ks = 0; ks < 128; ks += 2) {
        RLDA(1, ks + 1); RLDB(1, ks + 1);
        RMMAS(0);
        if (ks + 2 < 128) { RLDA(0, ks + 2); RLDB(0, ks + 2); }
        RMMAS(1);
    }

#pragma unroll
    for (int mt = 0; mt < 4; mt++)
#pragma unroll
        for (int nt = 0; nt < 4; nt++) {
            int row = wmi * 64 + mt * 16 + (lane >> 2);
            int n = wni * 32 + nt * 8 + ((lane & 3) << 1);
            float2 br = *(const float2*)&b_root[n];
            *(float2*)&out[(b0 + row) * NOUT + n] =
                make_float2(racc[mt][nt][0] + br.x, racc[mt][nt][1] + br.y);
            *(float2*)&out[(b0 + row + 8) * NOUT + n] =
                make_float2(racc[mt][nt][2] + br.x, racc[mt][nt][3] + br.y);
        }
}

// ---------------- launch ----------------
extern "C" void kernel_launch(void* const* d_in, const int* in_sizes, int n_in,
                              void* d_out, int out_size) {
    const float* x      = (const float*)d_in[0];
    const float* w_inp  = (const float*)d_in[1];
    const float* pbias  = (const float*)d_in[2];
    const float* W_mid  = (const float*)d_in[3];
    const float* b_mid  = (const float*)d_in[4];
    const float* W_root = (const float*)d_in[5];
    const float* b_root = (const float*)d_in[6];
    float* out = (float*)d_out;

    int batch = in_sizes[0] / INDIM;   // 16384
    int btiles = batch / 128;          // 128

    const int PREP_SMEM = 67584 + 1024;   // halves + partial-sum floats
    cudaFuncSetAttribute(k_prep, cudaFuncAttributeMaxDynamicSharedMemorySize, PREP_SMEM);
    cudaFuncSetAttribute(k_mid,  cudaFuncAttributeMaxDynamicSharedMemorySize, MID_SMEM);

    k_prep<<<48, 256, PREP_SMEM>>>(w_inp, pbias, W_mid, b_mid, W_root);
    k_mid<<<btiles, 512, MID_SMEM>>>(x);
    k_root<<<btiles, 512>>>(out, b_root);
}

// round 10
// speedup vs baseline: 1.5681x; 1.4459x over previous
#include <cuda_runtime.h>
#include <cuda_fp16.h>
#include <cstdint>

// ---------------- problem constants ----------------
#define INDIM 4096
#define NGRP  16
#define NOUT  256

// ---------------- device scratch ----------------
__device__ float  g_cmid[NGRP][128];        // folded constants
__device__ uint2  g_WmF[NGRP][16][16][32];  // mid B frags: [g][n8][k16][lane] -> (b0,b1)
__device__ uint2  g_WrF[32][128][32];       // root B frags: [n8][k16][lane] -> (b0,b1)
__device__ uint4  g_midP[1024][128][32];    // root A frags: [b16][k16][lane] -> (a0..a3)

// ---------------- helpers ----------------
__device__ __forceinline__ unsigned smem_u32(const void* p) {
    unsigned a;
    asm("{ .reg .u64 t; cvta.to.shared.u64 t, %1; cvt.u32.u64 %0, t; }" : "=r"(a) : "l"(p));
    return a;
}
__device__ __forceinline__ void ldsm4(unsigned& r0, unsigned& r1, unsigned& r2, unsigned& r3,
                                      unsigned addr) {
    asm volatile("ldmatrix.sync.aligned.m8n8.x4.shared.b16 {%0,%1,%2,%3}, [%4];"
                 : "=r"(r0), "=r"(r1), "=r"(r2), "=r"(r3) : "r"(addr));
}
__device__ __forceinline__ void mma16816(float* c, const unsigned* a, unsigned b0, unsigned b1) {
    asm volatile(
        "mma.sync.aligned.m16n8k16.row.col.f32.f16.f16.f32 "
        "{%0,%1,%2,%3},{%4,%5,%6,%7},{%8,%9},{%0,%1,%2,%3};"
        : "+f"(c[0]), "+f"(c[1]), "+f"(c[2]), "+f"(c[3])
        : "r"(a[0]), "r"(a[1]), "r"(a[2]), "r"(a[3]), "r"(b0), "r"(b1));
}
__device__ __forceinline__ float fast_tanh(float v) {
    v = fminf(fmaxf(v, -15.f), 15.f);
    float e = __expf(2.f * v);
    return __fdividef(e - 1.f, e + 1.f);
}
__device__ __forceinline__ unsigned packf2(float lo, float hi) {
    __half2 h = __floats2half2_rn(lo, hi);
    return *(unsigned*)&h;
}

// ---------------- prep ----------------
// blocks [0,256):   g_cmid (warp per (g,n))
// blocks [256,320): g_WmF (64 blocks: 4 k-slabs per group)
// blocks [320,352): g_WrF (32 blocks: 64-k slab each)
__global__ void k_prep(const float* __restrict__ w_inp, const float* __restrict__ pbias,
                       const float* __restrict__ W_mid, const float* __restrict__ b_mid,
                       const float* __restrict__ W_root) {
    extern __shared__ float sm[];
    int tid = threadIdx.x;
    if (blockIdx.x < 256) {
        int w = (blockIdx.x * 256 + tid) >> 5;
        int lane = tid & 31;
        int g = w >> 7, n = w & 127;
        float sum = 0.f;
#pragma unroll
        for (int l = 0; l < 8; l++) {
            int j = l * 32 + lane;
            sum += pbias[(g * 256 + j) >> 6] * W_mid[(g * 256 + j) * 128 + n];
        }
#pragma unroll
        for (int o = 16; o > 0; o >>= 1) sum += __shfl_xor_sync(0xffffffffu, sum, o);
        if (lane == 0) g_cmid[g][n] = sum + b_mid[g * 128 + n];
    } else if (blockIdx.x < 320) {
        int b = blockIdx.x - 256;
        int g = b >> 2, kslab = b & 3;           // k in [kslab*64, +64)
        int kg = kslab * 64;
        __half* smh = (__half*)sm;               // [64 k][132 n] halves
#pragma unroll
        for (int i = 0; i < 32; i++) {
            int flat = i * 256 + tid;
            int k = flat >> 7, n = flat & 127;
            smh[k * 132 + n] = __float2half_rn(
                w_inp[g * 256 + kg + k] * W_mid[(g * 256 + kg + k) * 128 + n]);
        }
        __syncthreads();
        int lane = tid & 31, w = tid >> 5;       // 8 warps x 8 tiles = 64 (n8,k16l)
#pragma unroll
        for (int i = 0; i < 8; i++) {
            int t = w * 8 + i;
            int n8 = t & 15, k16l = t >> 4;      // k16l 0..3
            int n = n8 * 8 + (lane >> 2);
            int kl = k16l * 16 + ((lane & 3) << 1);
            unsigned w0 = packf2(__half2float(smh[kl * 132 + n]),
                                 __half2float(smh[(kl + 1) * 132 + n]));
            unsigned w1 = packf2(__half2float(smh[(kl + 8) * 132 + n]),
                                 __half2float(smh[(kl + 9) * 132 + n]));
            g_WmF[g][n8][kslab * 4 + k16l][lane] = make_uint2(w0, w1);
        }
    } else {
        int kb = blockIdx.x - 320;               // 0..31, k slab
#pragma unroll
        for (int j = 0; j < 64; j++) {
            int flat = j * 256 + tid;
            int kl = flat >> 8, n = flat & 255;
            sm[kl * 257 + n] = W_root[(kb * 64 + kl) * 256 + n];
        }
        __syncthreads();
        int lane = tid & 31, w = tid >> 5;
#pragma unroll
        for (int i = 0; i < 16; i++) {
            int t = w * 16 + i;
            int n8 = t & 31, k16l = t >> 5;
            unsigned wd[2];
#pragma unroll
            for (int j = 0; j < 2; j++) {
                int kl = k16l * 16 + j * 8 + ((lane & 3) << 1);
                int n = n8 * 8 + (lane >> 2);
                wd[j] = packf2(sm[kl * 257 + n], sm[(kl + 1) * 257 + n]);
            }
            g_WrF[n8][kb * 4 + k16l][lane] = make_uint2(wd[0], wd[1]);
        }
    }
}

// ================= MID GEMM: 64 rows x 128 n x K=256 (one group per CTA) ==============
// 256 threads, 8 warps: Mw=2 x Nw=4, warp tile 32x32. A via smem+ldsm, B frag-direct LDG.
// smem: 2 x [64][72] f16 = 18432 B (x double buffer only)
#define MSTR 72
#define MXBUF 9216u
#define MID_SMEM 18432

__global__ void __launch_bounds__(256, 2) k_mid(const float* __restrict__ x) {
    extern __shared__ char smem[];
    unsigned sb = smem_u32(smem);
    const int tid = threadIdx.x, lane = tid & 31, wid = tid >> 5;
    const int wmi = wid & 1, wni = wid >> 1;      // 2 M-warps x 4 N-warps
    const long long b0 = (long long)blockIdx.x * 64;
    const int g = blockIdx.y;

    const uint2* bp = &g_WmF[g][wni * 4][0][lane];   // + nt*512 + k16*32 (uint2 units)

    float macc[2][4][4];
#pragma unroll
    for (int i = 0; i < 2; i++)
#pragma unroll
        for (int j = 0; j < 4; j++)
#pragma unroll
            for (int q = 0; q < 4; q++) macc[i][j][q] = 0.f;

    // x chunk LDG: 1024 float4 over [64 rows][64 k] f32; idx = tid + j*256
    float4 xv[4];
#define LDX(CC)                                                                       \
    { const float* xc = x + b0 * INDIM + g * 256 + (CC) * 64;                         \
      _Pragma("unroll") for (int j = 0; j < 4; j++) {                                 \
          int idx = tid + j * 256;                                                    \
          int r = idx >> 4, f4 = idx & 15;                                            \
          xv[j] = *(const float4*)(xc + (long long)r * INDIM + f4 * 4);               \
      } }
#define STX(BUF)                                                                      \
    { unsigned xbuf = sb + (BUF) * MXBUF;                                             \
      _Pragma("unroll") for (int j = 0; j < 4; j++) {                                 \
          int idx = tid + j * 256;                                                    \
          int r = idx >> 4, f4 = idx & 15;                                            \
          unsigned h0 = packf2(xv[j].x, xv[j].y), h1 = packf2(xv[j].z, xv[j].w);      \
          asm volatile("st.shared.v2.b32 [%0], {%1,%2};"                              \
                       :: "r"(xbuf + (unsigned)(r * MSTR + f4 * 4) * 2u),             \
                          "r"(h0), "r"(h1));                                          \
      } }

    LDX(0);
#pragma unroll
    for (int c = 0; c < 4; c++) {
        const int buf = c & 1;
        STX(buf);
        if (c < 3) LDX(c + 1);
        // B frags for this chunk — issued before the barrier, latency hides in sync
        uint2 bf[4][4];
#pragma unroll
        for (int ks = 0; ks < 4; ks++)
#pragma unroll
            for (int nt = 0; nt < 4; nt++)
                bf[ks][nt] = bp[nt * 512 + (c * 4 + ks) * 32];
        __syncthreads();

        unsigned xbuf = sb + buf * MXBUF;
        int arow = wmi * 32 + (lane & 15);
        int acol = ((lane >> 4) << 3);
#pragma unroll
        for (int ks = 0; ks < 4; ks++) {
            unsigned afr[2][4];
#pragma unroll
            for (int mt = 0; mt < 2; mt++)
                ldsm4(afr[mt][0], afr[mt][1], afr[mt][2], afr[mt][3],
                      xbuf + (unsigned)((arow + mt * 16) * MSTR + ks * 16 + acol) * 2u);
#pragma unroll
            for (int mt = 0; mt < 2; mt++)
#pragma unroll
                for (int nt = 0; nt < 4; nt++)
                    mma16816(macc[mt][nt], afr[mt], bf[ks][nt].x, bf[ks][nt].y);
        }
    }

    // epilogue: tanh + pack macc directly into root A-frag tiles (no smem, no sync)
    const int nbase = wni * 32 + ((lane & 3) << 1);
#pragma unroll
    for (int mt = 0; mt < 2; mt++) {
        int b16 = (int)(b0 >> 4) + wmi * 2 + mt;
#pragma unroll
        for (int ntp = 0; ntp < 2; ntp++) {
            unsigned wd[4];
#pragma unroll
            for (int h = 0; h < 2; h++) {
                int nt = ntp * 2 + h;
                float2 gc = *(const float2*)&g_cmid[g][nbase + nt * 8];
                float* cc = macc[mt][nt];
                wd[2 * h]     = packf2(fast_tanh(cc[0] + gc.x), fast_tanh(cc[1] + gc.y));
                wd[2 * h + 1] = packf2(fast_tanh(cc[2] + gc.x), fast_tanh(cc[3] + gc.y));
            }
            g_midP[b16][g * 8 + wni * 2 + ntp][lane] = make_uint4(wd[0], wd[1], wd[2], wd[3]);
        }
    }
}

// ================= ROOT GEMM: 128 rows x 256 n x K=2048, smem-free frag-direct ==========
__global__ void __launch_bounds__(512) k_root(float* __restrict__ out,
                                              const float* __restrict__ b_root) {
    const int tid = threadIdx.x, lane = tid & 31, wid = tid >> 5;
    const int wmi = wid & 1, wni = wid >> 1;      // 2 M-warps x 8 N-warps
    const long long b0 = (long long)blockIdx.x * 128;
    const int bt = blockIdx.x * 8;

    float racc[4][4][4];
#pragma unroll
    for (int i = 0; i < 4; i++)
#pragma unroll
        for (int j = 0; j < 4; j++)
#pragma unroll
            for (int q = 0; q < 4; q++) racc[i][j][q] = 0.f;

    const char* Ap = (const char*)&g_midP[bt + wmi * 4][0][lane];   // + mt*65536 + ks*512
    const char* Bp = (const char*)&g_WrF[wni * 4][0][lane];         // + nt*32768 + ks*256

    uint4 Af[2][4];
    uint2 Bf[2][4];
#define RLDA(BUF, KS)                                                                \
    { _Pragma("unroll") for (int mt = 0; mt < 4; mt++)                               \
          Af[BUF][mt] = *(const uint4*)(Ap + mt * 65536 + (KS) * 512); }
#define RLDB(BUF, KS)                                                                \
    { _Pragma("unroll") for (int nt = 0; nt < 4; nt++)                               \
          Bf[BUF][nt] = *(const uint2*)(Bp + nt * 32768 + (KS) * 256); }
#define RMMAS(BUF)                                                                   \
    { _Pragma("unroll") for (int mt = 0; mt < 4; mt++)                               \
          _Pragma("unroll") for (int nt = 0; nt < 4; nt++)                           \
              mma16816(racc[mt][nt], (const unsigned*)&Af[BUF][mt],                  \
                       Bf[BUF][nt].x, Bf[BUF][nt].y); }

    RLDA(0, 0); RLDB(0, 0);
#pragma unroll 1
    for (int ks = 0; ks < 128; ks += 2) {
        RLDA(1, ks + 1); RLDB(1, ks + 1);
        RMMAS(0);
        if (ks + 2 < 128) { RLDA(0, ks + 2); RLDB(0, ks + 2); }
        RMMAS(1);
    }

#pragma unroll
    for (int mt = 0; mt < 4; mt++)
#pragma unroll
        for (int nt = 0; nt < 4; nt++) {
            int row = wmi * 64 + mt * 16 + (lane >> 2);
            int n = wni * 32 + nt * 8 + ((lane & 3) << 1);
            float2 br = *(const float2*)&b_root[n];
            *(float2*)&out[(b0 + row) * NOUT + n] =
                make_float2(racc[mt][nt][0] + br.x, racc[mt][nt][1] + br.y);
            *(float2*)&out[(b0 + row + 8) * NOUT + n] =
                make_float2(racc[mt][nt][2] + br.x, racc[mt][nt][3] + br.y);
        }
}

// ---------------- launch ----------------
extern "C" void kernel_launch(void* const* d_in, const int* in_sizes, int n_in,
                              void* d_out, int out_size) {
    const float* x      = (const float*)d_in[0];
    const float* w_inp  = (const float*)d_in[1];
    const float* pbias  = (const float*)d_in[2];
    const float* W_mid  = (const float*)d_in[3];
    const float* b_mid  = (const float*)d_in[4];
    const float* W_root = (const float*)d_in[5];
    const float* b_root = (const float*)d_in[6];
    float* out = (float*)d_out;

    int batch = in_sizes[0] / INDIM;   // 16384

    const int PREP_SMEM = 64 * 257 * 4;   // 65792 (covers both transpose stages)
    cudaFuncSetAttribute(k_prep, cudaFuncAttributeMaxDynamicSharedMemorySize, PREP_SMEM);
    cudaFuncSetAttribute(k_mid,  cudaFuncAttributeMaxDynamicSharedMemorySize, MID_SMEM);

    k_prep<<<352, 256, PREP_SMEM>>>(w_inp, pbias, W_mid, b_mid, W_root);
    k_mid<<<dim3(batch / 64, NGRP), 256, MID_SMEM>>>(x);
    k_root<<<batch / 128, 512>>>(out, b_root);
}

// round 11
// speedup vs baseline: 1.6044x; 1.0231x over previous
#include <cuda_runtime.h>
#include <cuda_fp16.h>
#include <cstdint>

// ---------------- problem constants ----------------
#define INDIM 4096
#define NGRP  16
#define NOUT  256

// ---------------- device scratch ----------------
__device__ float  g_cmid[NGRP][128];        // folded constants
__device__ uint2  g_WmF[NGRP][16][16][32];  // mid B frags: [g][n8][k16][lane] -> (b0,b1)
__device__ uint2  g_WrF[32][128][32];       // root B frags: [n8][k16][lane] -> (b0,b1)
__device__ uint4  g_midP[1024][128][32];    // root A frags: [b16][k16][lane] -> (a0..a3)

// ---------------- helpers ----------------
__device__ __forceinline__ unsigned smem_u32(const void* p) {
    unsigned a;
    asm("{ .reg .u64 t; cvta.to.shared.u64 t, %1; cvt.u32.u64 %0, t; }" : "=r"(a) : "l"(p));
    return a;
}
__device__ __forceinline__ void ldsm4(unsigned& r0, unsigned& r1, unsigned& r2, unsigned& r3,
                                      unsigned addr) {
    asm volatile("ldmatrix.sync.aligned.m8n8.x4.shared.b16 {%0,%1,%2,%3}, [%4];"
                 : "=r"(r0), "=r"(r1), "=r"(r2), "=r"(r3) : "r"(addr));
}
__device__ __forceinline__ void mma16816(float* c, const unsigned* a, unsigned b0, unsigned b1) {
    asm volatile(
        "mma.sync.aligned.m16n8k16.row.col.f32.f16.f16.f32 "
        "{%0,%1,%2,%3},{%4,%5,%6,%7},{%8,%9},{%0,%1,%2,%3};"
        : "+f"(c[0]), "+f"(c[1]), "+f"(c[2]), "+f"(c[3])
        : "r"(a[0]), "r"(a[1]), "r"(a[2]), "r"(a[3]), "r"(b0), "r"(b1));
}
__device__ __forceinline__ float fast_tanh(float v) {
    v = fminf(fmaxf(v, -15.f), 15.f);
    float e = __expf(2.f * v);
    return __fdividef(e - 1.f, e + 1.f);
}
__device__ __forceinline__ unsigned packf2(float lo, float hi) {
    __half2 h = __floats2half2_rn(lo, hi);
    return *(unsigned*)&h;
}

// ---------------- prep ----------------
// blocks [0,256):   g_cmid (warp per (g,n))
// blocks [256,320): g_WmF (64 blocks: 4 k-slabs per group)
// blocks [320,352): g_WrF (32 blocks: 64-k slab each)
__global__ void k_prep(const float* __restrict__ w_inp, const float* __restrict__ pbias,
                       const float* __restrict__ W_mid, const float* __restrict__ b_mid,
                       const float* __restrict__ W_root) {
    extern __shared__ float sm[];
    int tid = threadIdx.x;
    if (blockIdx.x < 256) {
        int w = (blockIdx.x * 256 + tid) >> 5;
        int lane = tid & 31;
        int g = w >> 7, n = w & 127;
        float sum = 0.f;
#pragma unroll
        for (int l = 0; l < 8; l++) {
            int j = l * 32 + lane;
            sum += pbias[(g * 256 + j) >> 6] * W_mid[(g * 256 + j) * 128 + n];
        }
#pragma unroll
        for (int o = 16; o > 0; o >>= 1) sum += __shfl_xor_sync(0xffffffffu, sum, o);
        if (lane == 0) g_cmid[g][n] = sum + b_mid[g * 128 + n];
    } else if (blockIdx.x < 320) {
        int b = blockIdx.x - 256;
        int g = b >> 2, kslab = b & 3;           // k in [kslab*64, +64)
        int kg = kslab * 64;
        __half* smh = (__half*)sm;               // [64 k][132 n] halves
#pragma unroll
        for (int i = 0; i < 32; i++) {
            int flat = i * 256 + tid;
            int k = flat >> 7, n = flat & 127;
            smh[k * 132 + n] = __float2half_rn(
                w_inp[g * 256 + kg + k] * W_mid[(g * 256 + kg + k) * 128 + n]);
        }
        __syncthreads();
        int lane = tid & 31, w = tid >> 5;       // 8 warps x 8 tiles = 64 (n8,k16l)
#pragma unroll
        for (int i = 0; i < 8; i++) {
            int t = w * 8 + i;
            int n8 = t & 15, k16l = t >> 4;      // k16l 0..3
            int n = n8 * 8 + (lane >> 2);
            int kl = k16l * 16 + ((lane & 3) << 1);
            unsigned w0 = packf2(__half2float(smh[kl * 132 + n]),
                                 __half2float(smh[(kl + 1) * 132 + n]));
            unsigned w1 = packf2(__half2float(smh[(kl + 8) * 132 + n]),
                                 __half2float(smh[(kl + 9) * 132 + n]));
            g_WmF[g][n8][kslab * 4 + k16l][lane] = make_uint2(w0, w1);
        }
    } else {
        int kb = blockIdx.x - 320;               // 0..31, k slab
#pragma unroll
        for (int j = 0; j < 64; j++) {
            int flat = j * 256 + tid;
            int kl = flat >> 8, n = flat & 255;
            sm[kl * 257 + n] = W_root[(kb * 64 + kl) * 256 + n];
        }
        __syncthreads();
        int lane = tid & 31, w = tid >> 5;
#pragma unroll
        for (int i = 0; i < 16; i++) {
            int t = w * 16 + i;
            int n8 = t & 31, k16l = t >> 5;
            unsigned wd[2];
#pragma unroll
            for (int j = 0; j < 2; j++) {
                int kl = k16l * 16 + j * 8 + ((lane & 3) << 1);
                int n = n8 * 8 + (lane >> 2);
                wd[j] = packf2(sm[kl * 257 + n], sm[(kl + 1) * 257 + n]);
            }
            g_WrF[n8][kb * 4 + k16l][lane] = make_uint2(wd[0], wd[1]);
        }
    }
}

// ================= MID GEMM: 64 rows x 128 n x K=256 (one group per CTA) ==============
// 256 threads, 8 warps: Mw=2 x Nw=4, warp tile 32x32. A via smem+ldsm, B frag-direct LDG.
// 3 CTAs/SM (register diet: fp16-at-load x buffer, 2-deep B pipeline).
// smem: 2 x [64][72] f16 = 18432 B
#define MSTR 72
#define MXBUF 9216u
#define MID_SMEM 18432

__global__ void __launch_bounds__(256, 3) k_mid(const float* __restrict__ x) {
    extern __shared__ char smem[];
    unsigned sb = smem_u32(smem);
    const int tid = threadIdx.x, lane = tid & 31, wid = tid >> 5;
    const int wmi = wid & 1, wni = wid >> 1;      // 2 M-warps x 4 N-warps
    const long long b0 = (long long)blockIdx.x * 64;
    const int g = blockIdx.y;

    const uint2* bp = &g_WmF[g][wni * 4][0][lane];   // + nt*512 + k16*32 (uint2 units)

    float macc[2][4][4];
#pragma unroll
    for (int i = 0; i < 2; i++)
#pragma unroll
        for (int j = 0; j < 4; j++)
#pragma unroll
            for (int q = 0; q < 4; q++) macc[i][j][q] = 0.f;

    // x chunk: 1024 float4 over [64 rows][64 k] f32; converted to fp16 at load (8 regs)
    uint2 xh[4];
#define LDX(CC)                                                                       \
    { const float* xc = x + b0 * INDIM + g * 256 + (CC) * 64;                         \
      _Pragma("unroll") for (int j = 0; j < 4; j++) {                                 \
          int idx = tid + j * 256;                                                    \
          int r = idx >> 4, f4 = idx & 15;                                            \
          float4 v = *(const float4*)(xc + (long long)r * INDIM + f4 * 4);            \
          xh[j] = make_uint2(packf2(v.x, v.y), packf2(v.z, v.w));                     \
      } }
#define STX(BUF)                                                                      \
    { unsigned xbuf = sb + (BUF) * MXBUF;                                             \
      _Pragma("unroll") for (int j = 0; j < 4; j++) {                                 \
          int idx = tid + j * 256;                                                    \
          int r = idx >> 4, f4 = idx & 15;                                            \
          asm volatile("st.shared.v2.b32 [%0], {%1,%2};"                              \
                       :: "r"(xbuf + (unsigned)(r * MSTR + f4 * 4) * 2u),             \
                          "r"(xh[j].x), "r"(xh[j].y));                                \
      } }

    LDX(0);
#pragma unroll
    for (int c = 0; c < 4; c++) {
        const int buf = c & 1;
        STX(buf);
        if (c < 3) LDX(c + 1);
        // B frags, 2-deep pipeline: ks=0,1 before the barrier (latency hides in sync)
        uint2 bf[2][4];
#pragma unroll
        for (int nt = 0; nt < 4; nt++) bf[0][nt] = bp[nt * 512 + (c * 4 + 0) * 32];
#pragma unroll
        for (int nt = 0; nt < 4; nt++) bf[1][nt] = bp[nt * 512 + (c * 4 + 1) * 32];
        __syncthreads();

        unsigned xbuf = sb + buf * MXBUF;
        int arow = wmi * 32 + (lane & 15);
        int acol = ((lane >> 4) << 3);
#pragma unroll
        for (int ks = 0; ks < 4; ks++) {
            unsigned afr[2][4];
#pragma unroll
            for (int mt = 0; mt < 2; mt++)
                ldsm4(afr[mt][0], afr[mt][1], afr[mt][2], afr[mt][3],
                      xbuf + (unsigned)((arow + mt * 16) * MSTR + ks * 16 + acol) * 2u);
#pragma unroll
            for (int mt = 0; mt < 2; mt++)
#pragma unroll
                for (int nt = 0; nt < 4; nt++)
                    mma16816(macc[mt][nt], afr[mt], bf[ks & 1][nt].x, bf[ks & 1][nt].y);
            if (ks < 2) {
#pragma unroll
                for (int nt = 0; nt < 4; nt++)
                    bf[ks & 1][nt] = bp[nt * 512 + (c * 4 + ks + 2) * 32];
            }
        }
    }

    // epilogue: tanh + pack macc directly into root A-frag tiles (no smem, no sync)
    const int nbase = wni * 32 + ((lane & 3) << 1);
#pragma unroll
    for (int mt = 0; mt < 2; mt++) {
        int b16 = (int)(b0 >> 4) + wmi * 2 + mt;
#pragma unroll
        for (int ntp = 0; ntp < 2; ntp++) {
            unsigned wd[4];
#pragma unroll
            for (int h = 0; h < 2; h++) {
                int nt = ntp * 2 + h;
                float2 gc = *(const float2*)&g_cmid[g][nbase + nt * 8];
                float* cc = macc[mt][nt];
                wd[2 * h]     = packf2(fast_tanh(cc[0] + gc.x), fast_tanh(cc[1] + gc.y));
                wd[2 * h + 1] = packf2(fast_tanh(cc[2] + gc.x), fast_tanh(cc[3] + gc.y));
            }
            g_midP[b16][g * 8 + wni * 2 + ntp][lane] = make_uint4(wd[0], wd[1], wd[2], wd[3]);
        }
    }
}

// ================= ROOT GEMM: 128 rows x 256 n x K=2048, smem-free frag-direct ==========
__global__ void __launch_bounds__(512) k_root(float* __restrict__ out,
                                              const float* __restrict__ b_root) {
    const int tid = threadIdx.x, lane = tid & 31, wid = tid >> 5;
    const int wmi = wid & 1, wni = wid >> 1;      // 2 M-warps x 8 N-warps
    const long long b0 = (long long)blockIdx.x * 128;
    const int bt = blockIdx.x * 8;

    float racc[4][4][4];
#pragma unroll
    for (int i = 0; i < 4; i++)
#pragma unroll
        for (int j = 0; j < 4; j++)
#pragma unroll
            for (int q = 0; q < 4; q++) racc[i][j][q] = 0.f;

    const char* Ap = (const char*)&g_midP[bt + wmi * 4][0][lane];   // + mt*65536 + ks*512
    const char* Bp = (const char*)&g_WrF[wni * 4][0][lane];         // + nt*32768 + ks*256

    uint4 Af[2][4];
    uint2 Bf[2][4];
#define RLDA(BUF, KS)                                                                \
    { _Pragma("unroll") for (int mt = 0; mt < 4; mt++)                               \
          Af[BUF][mt] = *(const uint4*)(Ap + mt * 65536 + (KS) * 512); }
#define RLDB(BUF, KS)                                                                \
    { _Pragma("unroll") for (int nt = 0; nt < 4; nt++)                               \
          Bf[BUF][nt] = *(const uint2*)(Bp + nt * 32768 + (KS) * 256); }
#define RMMAS(BUF)                                                                   \
    { _Pragma("unroll") for (int mt = 0; mt < 4; mt++)                               \
          _Pragma("unroll") for (int nt = 0; nt < 4; nt++)                           \
              mma16816(racc[mt][nt], (const unsigned*)&Af[BUF][mt],                  \
                       Bf[BUF][nt].x, Bf[BUF][nt].y); }

    RLDA(0, 0); RLDB(0, 0);
#pragma unroll 1
    for (int ks = 0; ks < 128; ks += 2) {
        RLDA(1, ks + 1); RLDB(1, ks + 1);
        RMMAS(0);
        if (ks + 2 < 128) { RLDA(0, ks + 2); RLDB(0, ks + 2); }
        RMMAS(1);
    }

#pragma unroll
    for (int mt = 0; mt < 4; mt++)
#pragma unroll
        for (int nt = 0; nt < 4; nt++) {
            int row = wmi * 64 + mt * 16 + (lane >> 2);
            int n = wni * 32 + nt * 8 + ((lane & 3) << 1);
            float2 br = *(const float2*)&b_root[n];
            *(float2*)&out[(b0 + row) * NOUT + n] =
                make_float2(racc[mt][nt][0] + br.x, racc[mt][nt][1] + br.y);
            *(float2*)&out[(b0 + row + 8) * NOUT + n] =
                make_float2(racc[mt][nt][2] + br.x, racc[mt][nt][3] + br.y);
        }
}

// ---------------- launch ----------------
extern "C" void kernel_launch(void* const* d_in, const int* in_sizes, int n_in,
                              void* d_out, int out_size) {
    const float* x      = (const float*)d_in[0];
    const float* w_inp  = (const float*)d_in[1];
    const float* pbias  = (const float*)d_in[2];
    const float* W_mid  = (const float*)d_in[3];
    const float* b_mid  = (const float*)d_in[4];
    const float* W_root = (const float*)d_in[5];
    const float* b_root = (const float*)d_in[6];
    float* out = (float*)d_out;

    int batch = in_sizes[0] / INDIM;   // 16384

    const int PREP_SMEM = 64 * 257 * 4;   // 65792
    cudaFuncSetAttribute(k_prep, cudaFuncAttributeMaxDynamicSharedMemorySize, PREP_SMEM);
    cudaFuncSetAttribute(k_mid,  cudaFuncAttributeMaxDynamicSharedMemorySize, MID_SMEM);

    k_prep<<<352, 256, PREP_SMEM>>>(w_inp, pbias, W_mid, b_mid, W_root);
    k_mid<<<dim3(batch / 64, NGRP), 256, MID_SMEM>>>(x);
    k_root<<<batch / 128, 512>>>(out, b_root);
}

// round 12
// speedup vs baseline: 1.6210x; 1.0103x over previous
#include <cuda_runtime.h>
#include <cuda_fp16.h>
#include <cstdint>

// ---------------- problem constants ----------------
#define INDIM 4096
#define NGRP  16
#define NOUT  256

// ---------------- device scratch ----------------
__device__ float  g_cmid[NGRP][128];        // folded constants
__device__ uint2  g_WmF[NGRP][16][16][32];  // mid B frags: [g][n8][k16][lane] -> (b0,b1)
__device__ uint2  g_WrF[32][128][32];       // root B frags: [n8][k16][lane] -> (b0,b1)
__device__ uint4  g_midP[1024][128][32];    // root A frags: [b16][k16][lane] -> (a0..a3)

// ---------------- helpers ----------------
__device__ __forceinline__ unsigned smem_u32(const void* p) {
    unsigned a;
    asm("{ .reg .u64 t; cvta.to.shared.u64 t, %1; cvt.u32.u64 %0, t; }" : "=r"(a) : "l"(p));
    return a;
}
__device__ __forceinline__ void ldsm4(unsigned& r0, unsigned& r1, unsigned& r2, unsigned& r3,
                                      unsigned addr) {
    asm volatile("ldmatrix.sync.aligned.m8n8.x4.shared.b16 {%0,%1,%2,%3}, [%4];"
                 : "=r"(r0), "=r"(r1), "=r"(r2), "=r"(r3) : "r"(addr));
}
__device__ __forceinline__ void mma16816(float* c, const unsigned* a, unsigned b0, unsigned b1) {
    asm volatile(
        "mma.sync.aligned.m16n8k16.row.col.f32.f16.f16.f32 "
        "{%0,%1,%2,%3},{%4,%5,%6,%7},{%8,%9},{%0,%1,%2,%3};"
        : "+f"(c[0]), "+f"(c[1]), "+f"(c[2]), "+f"(c[3])
        : "r"(a[0]), "r"(a[1]), "r"(a[2]), "r"(a[3]), "r"(b0), "r"(b1));
}
__device__ __forceinline__ float fast_tanh(float v) {
    v = fminf(fmaxf(v, -15.f), 15.f);
    float e = __expf(2.f * v);
    return __fdividef(e - 1.f, e + 1.f);
}
__device__ __forceinline__ unsigned packf2(float lo, float hi) {
    __half2 h = __floats2half2_rn(lo, hi);
    return *(unsigned*)&h;
}

// ---------------- prep ----------------
// blocks [0,256):   g_cmid (warp per (g,n))
// blocks [256,320): g_WmF (64 blocks: 4 k-slabs per group)
// blocks [320,352): g_WrF (32 blocks: 64-k slab each)
__global__ void k_prep(const float* __restrict__ w_inp, const float* __restrict__ pbias,
                       const float* __restrict__ W_mid, const float* __restrict__ b_mid,
                       const float* __restrict__ W_root) {
    extern __shared__ float sm[];
    int tid = threadIdx.x;
    if (blockIdx.x < 256) {
        int w = (blockIdx.x * 256 + tid) >> 5;
        int lane = tid & 31;
        int g = w >> 7, n = w & 127;
        float sum = 0.f;
#pragma unroll
        for (int l = 0; l < 8; l++) {
            int j = l * 32 + lane;
            sum += pbias[(g * 256 + j) >> 6] * W_mid[(g * 256 + j) * 128 + n];
        }
#pragma unroll
        for (int o = 16; o > 0; o >>= 1) sum += __shfl_xor_sync(0xffffffffu, sum, o);
        if (lane == 0) g_cmid[g][n] = sum + b_mid[g * 128 + n];
    } else if (blockIdx.x < 320) {
        int b = blockIdx.x - 256;
        int g = b >> 2, kslab = b & 3;           // k in [kslab*64, +64)
        int kg = kslab * 64;
        __half* smh = (__half*)sm;               // [64 k][132 n] halves
#pragma unroll
        for (int i = 0; i < 32; i++) {
            int flat = i * 256 + tid;
            int k = flat >> 7, n = flat & 127;
            smh[k * 132 + n] = __float2half_rn(
                w_inp[g * 256 + kg + k] * W_mid[(g * 256 + kg + k) * 128 + n]);
        }
        __syncthreads();
        int lane = tid & 31, w = tid >> 5;       // 8 warps x 8 tiles = 64 (n8,k16l)
#pragma unroll
        for (int i = 0; i < 8; i++) {
            int t = w * 8 + i;
            int n8 = t & 15, k16l = t >> 4;      // k16l 0..3
            int n = n8 * 8 + (lane >> 2);
            int kl = k16l * 16 + ((lane & 3) << 1);
            unsigned w0 = packf2(__half2float(smh[kl * 132 + n]),
                                 __half2float(smh[(kl + 1) * 132 + n]));
            unsigned w1 = packf2(__half2float(smh[(kl + 8) * 132 + n]),
                                 __half2float(smh[(kl + 9) * 132 + n]));
            g_WmF[g][n8][kslab * 4 + k16l][lane] = make_uint2(w0, w1);
        }
    } else {
        int kb = blockIdx.x - 320;               // 0..31, k slab
#pragma unroll
        for (int j = 0; j < 64; j++) {
            int flat = j * 256 + tid;
            int kl = flat >> 8, n = flat & 255;
            sm[kl * 257 + n] = W_root[(kb * 64 + kl) * 256 + n];
        }
        __syncthreads();
        int lane = tid & 31, w = tid >> 5;
#pragma unroll
        for (int i = 0; i < 16; i++) {
            int t = w * 16 + i;
            int n8 = t & 31, k16l = t >> 5;
            unsigned wd[2];
#pragma unroll
            for (int j = 0; j < 2; j++) {
                int kl = k16l * 16 + j * 8 + ((lane & 3) << 1);
                int n = n8 * 8 + (lane >> 2);
                wd[j] = packf2(sm[kl * 257 + n], sm[(kl + 1) * 257 + n]);
            }
            g_WrF[n8][kb * 4 + k16l][lane] = make_uint2(wd[0], wd[1]);
        }
    }
}

// ================= MID GEMM: 64 rows x 128 n x K=256, single-stage, ONE barrier ========
// 256 threads, 8 warps: Mw=2 x Nw=4, warp tile 32x32. A via smem+ldsm, B frag-direct LDG.
// Entire 64x256 x tile staged at once (MLP 16), one __syncthreads, 16 k16 MMA steps.
// smem: [64][264] f16 = 33792 B; 2 CTAs/SM.
#define MSTR 264
#define MID_SMEM 33792

__global__ void __launch_bounds__(256, 2) k_mid(const float* __restrict__ x) {
    extern __shared__ char smem[];
    unsigned sb = smem_u32(smem);
    const int tid = threadIdx.x, lane = tid & 31, wid = tid >> 5;
    const int wmi = wid & 1, wni = wid >> 1;      // 2 M-warps x 4 N-warps
    const long long b0 = (long long)blockIdx.x * 64;
    const int g = blockIdx.y;

    const uint2* bp = &g_WmF[g][wni * 4][0][lane];   // + nt*512 + k16*32 (uint2 units)

    // ---- stage entire x tile: 4096 float4, 16 per thread, fp16 conversion at load ----
    const float* xc = x + b0 * INDIM + g * 256;
    uint2 xh[16];
#pragma unroll
    for (int j = 0; j < 16; j++) {
        int idx = tid + j * 256;
        int r = idx >> 6, f4 = idx & 63;          // 64 float4 per row
        float4 v = *(const float4*)(xc + (long long)r * INDIM + f4 * 4);
        xh[j] = make_uint2(packf2(v.x, v.y), packf2(v.z, v.w));
    }
#pragma unroll
    for (int j = 0; j < 16; j++) {
        int idx = tid + j * 256;
        int r = idx >> 6, f4 = idx & 63;
        asm volatile("st.shared.v2.b32 [%0], {%1,%2};"
                     :: "r"(sb + (unsigned)(r * MSTR + f4 * 4) * 2u),
                        "r"(xh[j].x), "r"(xh[j].y));
    }

    float macc[2][4][4];
#pragma unroll
    for (int i = 0; i < 2; i++)
#pragma unroll
        for (int j = 0; j < 4; j++)
#pragma unroll
            for (int q = 0; q < 4; q++) macc[i][j][q] = 0.f;

    // B frags for k16 = 0,1 issued before the barrier (latency hides in sync wait)
    uint2 bf[2][4];
#pragma unroll
    for (int nt = 0; nt < 4; nt++) bf[0][nt] = bp[nt * 512 + 0 * 32];
#pragma unroll
    for (int nt = 0; nt < 4; nt++) bf[1][nt] = bp[nt * 512 + 1 * 32];
    __syncthreads();                               // the ONLY barrier

    const int arow = wmi * 32 + (lane & 15);
    const int acol = ((lane >> 4) << 3);
#pragma unroll
    for (int ks = 0; ks < 16; ks++) {
        unsigned afr[2][4];
#pragma unroll
        for (int mt = 0; mt < 2; mt++)
            ldsm4(afr[mt][0], afr[mt][1], afr[mt][2], afr[mt][3],
                  sb + (unsigned)((arow + mt * 16) * MSTR + ks * 16 + acol) * 2u);
#pragma unroll
        for (int mt = 0; mt < 2; mt++)
#pragma unroll
            for (int nt = 0; nt < 4; nt++)
                mma16816(macc[mt][nt], afr[mt], bf[ks & 1][nt].x, bf[ks & 1][nt].y);
        if (ks < 14) {
#pragma unroll
            for (int nt = 0; nt < 4; nt++)
                bf[ks & 1][nt] = bp[nt * 512 + (ks + 2) * 32];
        }
    }

    // epilogue: tanh + pack macc directly into root A-frag tiles (no smem, no sync)
    const int nbase = wni * 32 + ((lane & 3) << 1);
#pragma unroll
    for (int mt = 0; mt < 2; mt++) {
        int b16 = (int)(b0 >> 4) + wmi * 2 + mt;
#pragma unroll
        for (int ntp = 0; ntp < 2; ntp++) {
            unsigned wd[4];
#pragma unroll
            for (int h = 0; h < 2; h++) {
                int nt = ntp * 2 + h;
                float2 gc = *(const float2*)&g_cmid[g][nbase + nt * 8];
                float* cc = macc[mt][nt];
                wd[2 * h]     = packf2(fast_tanh(cc[0] + gc.x), fast_tanh(cc[1] + gc.y));
                wd[2 * h + 1] = packf2(fast_tanh(cc[2] + gc.x), fast_tanh(cc[3] + gc.y));
            }
            g_midP[b16][g * 8 + wni * 2 + ntp][lane] = make_uint4(wd[0], wd[1], wd[2], wd[3]);
        }
    }
}

// ================= ROOT GEMM: 128 rows x 256 n x K=2048, smem-free frag-direct ==========
__global__ void __launch_bounds__(512) k_root(float* __restrict__ out,
                                              const float* __restrict__ b_root) {
    const int tid = threadIdx.x, lane = tid & 31, wid = tid >> 5;
    const int wmi = wid & 1, wni = wid >> 1;      // 2 M-warps x 8 N-warps
    const long long b0 = (long long)blockIdx.x * 128;
    const int bt = blockIdx.x * 8;

    float racc[4][4][4];
#pragma unroll
    for (int i = 0; i < 4; i++)
#pragma unroll
        for (int j = 0; j < 4; j++)
#pragma unroll
            for (int q = 0; q < 4; q++) racc[i][j][q] = 0.f;

    const char* Ap = (const char*)&g_midP[bt + wmi * 4][0][lane];   // + mt*65536 + ks*512
    const char* Bp = (const char*)&g_WrF[wni * 4][0][lane];         // + nt*32768 + ks*256

    uint4 Af[2][4];
    uint2 Bf[2][4];
#define RLDA(BUF, KS)                                                                \
    { _Pragma("unroll") for (int mt = 0; mt < 4; mt++)                               \
          Af[BUF][mt] = *(const uint4*)(Ap + mt * 65536 + (KS) * 512); }
#define RLDB(BUF, KS)                                                                \
    { _Pragma("unroll") for (int nt = 0; nt < 4; nt++)                               \
          Bf[BUF][nt] = *(const uint2*)(Bp + nt * 32768 + (KS) * 256); }
#define RMMAS(BUF)                                                                   \
    { _Pragma("unroll") for (int mt = 0; mt < 4; mt++)                               \
          _Pragma("unroll") for (int nt = 0; nt < 4; nt++)                           \
              mma16816(racc[mt][nt], (const unsigned*)&Af[BUF][mt],                  \
                       Bf[BUF][nt].x, Bf[BUF][nt].y); }

    RLDA(0, 0); RLDB(0, 0);
#pragma unroll 1
    for (int ks = 0; ks < 128; ks += 2) {
        RLDA(1, ks + 1); RLDB(1, ks + 1);
        RMMAS(0);
        if (ks + 2 < 128) { RLDA(0, ks + 2); RLDB(0, ks + 2); }
        RMMAS(1);
    }

#pragma unroll
    for (int mt = 0; mt < 4; mt++)
#pragma unroll
        for (int nt = 0; nt < 4; nt++) {
            int row = wmi * 64 + mt * 16 + (lane >> 2);
            int n = wni * 32 + nt * 8 + ((lane & 3) << 1);
            float2 br = *(const float2*)&b_root[n];
            *(float2*)&out[(b0 + row) * NOUT + n] =
                make_float2(racc[mt][nt][0] + br.x, racc[mt][nt][1] + br.y);
            *(float2*)&out[(b0 + row + 8) * NOUT + n] =
                make_float2(racc[mt][nt][2] + br.x, racc[mt][nt][3] + br.y);
        }
}

// ---------------- launch ----------------
extern "C" void kernel_launch(void* const* d_in, const int* in_sizes, int n_in,
                              void* d_out, int out_size) {
    const float* x      = (const float*)d_in[0];
    const float* w_inp  = (const float*)d_in[1];
    const float* pbias  = (const float*)d_in[2];
    const float* W_mid  = (const float*)d_in[3];
    const float* b_mid  = (const float*)d_in[4];
    const float* W_root = (const float*)d_in[5];
    const float* b_root = (const float*)d_in[6];
    float* out = (float*)d_out;

    int batch = in_sizes[0] / INDIM;   // 16384

    const int PREP_SMEM = 64 * 257 * 4;   // 65792
    cudaFuncSetAttribute(k_prep, cudaFuncAttributeMaxDynamicSharedMemorySize, PREP_SMEM);
    cudaFuncSetAttribute(k_mid,  cudaFuncAttributeMaxDynamicSharedMemorySize, MID_SMEM);

    k_prep<<<352, 256, PREP_SMEM>>>(w_inp, pbias, W_mid, b_mid, W_root);
    k_mid<<<dim3(batch / 64, NGRP), 256, MID_SMEM>>>(x);
    k_root<<<batch / 128, 512>>>(out, b_root);
}